// round 5
// baseline (speedup 1.0000x reference)
#include <cuda_runtime.h>

// CrimeModelLSTM: 2-layer LSTM (H=8), B=4096, T=512, FC head [4,8].
// 8 threads/element; thread j owns hidden unit j (gate rows j,8+j,16+j,24+j).
// R5 (= R4 retry, infra failure last round): split-accumulator trees for the
// gate dot products — L1 chain 9-deep -> 5, L2 chain 16-deep -> 4 (partials +
// packed-add tree). fma.rn.f32x2 gate-pairs, tanh.approx activations, and
// cross-layer software pipelining kept from R3.

typedef unsigned long long u64;

__device__ __forceinline__ u64 pk2(float lo, float hi) {
    u64 r; asm("mov.b64 %0, {%1,%2};" : "=l"(r) : "f"(lo), "f"(hi)); return r;
}
__device__ __forceinline__ void upk(u64 v, float& lo, float& hi) {
    asm("mov.b64 {%0,%1}, %2;" : "=f"(lo), "=f"(hi) : "l"(v));
}
__device__ __forceinline__ u64 fma2(u64 a, u64 b, u64 c) {
    u64 d; asm("fma.rn.f32x2 %0, %1, %2, %3;" : "=l"(d) : "l"(a), "l"(b), "l"(c)); return d;
}
__device__ __forceinline__ u64 mul2(u64 a, u64 b) {
    u64 d; asm("mul.rn.f32x2 %0, %1, %2;" : "=l"(d) : "l"(a), "l"(b)); return d;
}
__device__ __forceinline__ u64 add2(u64 a, u64 b) {
    u64 d; asm("add.rn.f32x2 %0, %1, %2;" : "=l"(d) : "l"(a), "l"(b)); return d;
}
__device__ __forceinline__ float tanhap(float x) {
    float r; asm("tanh.approx.f32 %0, %1;" : "=f"(r) : "f"(x)); return r;
}
// input pre-scaled by 0.5: sigmoid(2p) = 0.5 + 0.5*tanh(p)
__device__ __forceinline__ float sig_h(float p) { return fmaf(tanhap(p), 0.5f, 0.5f); }

__global__ void __launch_bounds__(32)
lstm2_kernel(const float* __restrict__ x,
             const float* __restrict__ Wih1, const float* __restrict__ Whh1,
             const float* __restrict__ bih1, const float* __restrict__ bhh1,
             const float* __restrict__ Wih2, const float* __restrict__ Whh2,
             const float* __restrict__ bih2, const float* __restrict__ bhh2,
             const float* __restrict__ Wfc,  const float* __restrict__ bfc,
             float* __restrict__ out)
{
    constexpr int T = 512;
    constexpr int H = 8;

    const int tid = blockIdx.x * 32 + threadIdx.x;
    const int e   = tid >> 3;   // batch element
    const int j   = tid & 7;    // hidden unit owned by this thread

    // per-gate scales: sigmoid rows (i,f,o) get 0.5 folded in; tanh row (g) 1.0
    const float gsc[4] = {0.5f, 0.5f, 1.0f, 0.5f};

    // ---- weights packed as gate pairs: pair0 = (i,f), pair1 = (g,o) ----
    u64 wh1p[2][H], wi2p[2][H], wh2p[2][H];
    u64 wx1p[2], bb1p[2], bb2p[2];
    #pragma unroll
    for (int p = 0; p < 2; p++) {
        const int gA = 2 * p, gB = 2 * p + 1;
        const int rA = gA * 8 + j, rB = gB * 8 + j;
        const float sA = gsc[gA], sB = gsc[gB];
        wx1p[p] = pk2(Wih1[rA] * sA, Wih1[rB] * sB);
        bb1p[p] = pk2((bih1[rA] + bhh1[rA]) * sA, (bih1[rB] + bhh1[rB]) * sB);
        bb2p[p] = pk2((bih2[rA] + bhh2[rA]) * sA, (bih2[rB] + bhh2[rB]) * sB);
        #pragma unroll
        for (int k = 0; k < H; k++) {
            wh1p[p][k] = pk2(Whh1[rA * H + k] * sA, Whh1[rB * H + k] * sB);
            wi2p[p][k] = pk2(Wih2[rA * H + k] * sA, Wih2[rB * H + k] * sB);
            wh2p[p][k] = pk2(Whh2[rA * H + k] * sA, Whh2[rB * H + k] * sB);
        }
    }

    // ---- state: h kept duplicated-packed (h,h) for FFMA2 operands ----
    u64 h1p[H], h2p[H];
    #pragma unroll
    for (int k = 0; k < H; k++) { h1p[k] = 0ull; h2p[k] = 0ull; }
    float c1 = 0.0f, c2 = 0.0f;

    const float4* __restrict__ xp = reinterpret_cast<const float4*>(x + (long)e * T);
    float4 xv = xp[0];

    // ---- prologue: L1 step 0 (h1 = 0: only x term) ----
    {
        u64 x2 = pk2(xv.x, xv.x);
        u64 P0 = fma2(wx1p[0], x2, bb1p[0]);
        u64 P1 = fma2(wx1p[1], x2, bb1p[1]);
        float a, b;
        upk(P0, a, b); const float i1 = sig_h(a), f1 = sig_h(b);
        upk(P1, a, b); const float g1 = tanhap(a), o1 = sig_h(b);
        c1 = fmaf(f1, c1, i1 * g1);
        const float h1o = o1 * tanhap(c1);
        #pragma unroll
        for (int k = 0; k < H; k++) {
            const float v = __shfl_sync(0xffffffffu, h1o, k, 8);
            h1p[k] = pk2(v, v);
        }
    }

    // ---- main loop: body computes L2(t) and L1(t+1); both consume h1(t) ----
    for (int tt = 0; tt < T / 4; ++tt) {
        const int nxt = (tt + 1 < T / 4) ? (tt + 1) : tt;
        float4 xn = xp[nxt];
        float xs[4] = {xv.y, xv.z, xv.w, xn.x};  // x for L1 step t+1

        #pragma unroll
        for (int q = 0; q < 4; q++) {
            u64 x2 = pk2(xs[q], xs[q]);

            // L1(t+1) partials: A (x-term + k=0..3), B (k=4..7)
            u64 A0 = fma2(wx1p[0], x2, bb1p[0]);
            u64 A1 = fma2(wx1p[1], x2, bb1p[1]);
            u64 B0, B1;
            // L2(t) partials: C (wi2, k=0..3), D (wi2, k=4..7),
            //                 E (wh2, k=0..3), F (wh2, k=4..7)
            u64 C0 = bb2p[0], C1 = bb2p[1];
            u64 D0, D1, E0, E1, F0, F1;

            #pragma unroll
            for (int k = 0; k < 4; k++) {
                const u64 h = h1p[k];
                C0 = fma2(wi2p[0][k], h, C0);
                C1 = fma2(wi2p[1][k], h, C1);
                A0 = fma2(wh1p[0][k], h, A0);
                A1 = fma2(wh1p[1][k], h, A1);
            }
            {   const u64 h = h1p[4];
                D0 = mul2(wi2p[0][4], h);
                D1 = mul2(wi2p[1][4], h);
                B0 = mul2(wh1p[0][4], h);
                B1 = mul2(wh1p[1][4], h);
            }
            #pragma unroll
            for (int k = 5; k < 8; k++) {
                const u64 h = h1p[k];
                D0 = fma2(wi2p[0][k], h, D0);
                D1 = fma2(wi2p[1][k], h, D1);
                B0 = fma2(wh1p[0][k], h, B0);
                B1 = fma2(wh1p[1][k], h, B1);
            }
            {   const u64 h = h2p[0];
                E0 = mul2(wh2p[0][0], h);
                E1 = mul2(wh2p[1][0], h);
            }
            #pragma unroll
            for (int k = 1; k < 4; k++) {
                const u64 h = h2p[k];
                E0 = fma2(wh2p[0][k], h, E0);
                E1 = fma2(wh2p[1][k], h, E1);
            }
            {   const u64 h = h2p[4];
                F0 = mul2(wh2p[0][4], h);
                F1 = mul2(wh2p[1][4], h);
            }
            #pragma unroll
            for (int k = 5; k < 8; k++) {
                const u64 h = h2p[k];
                F0 = fma2(wh2p[0][k], h, F0);
                F1 = fma2(wh2p[1][k], h, F1);
            }

            // combine partials (balanced trees)
            const u64 P1_0 = add2(A0, B0);
            const u64 P1_1 = add2(A1, B1);
            const u64 P2_0 = add2(add2(C0, D0), add2(E0, F0));
            const u64 P2_1 = add2(add2(C1, D1), add2(E1, F1));

            float a, b;
            upk(P1_0, a, b); const float i1 = sig_h(a), f1 = sig_h(b);
            upk(P1_1, a, b); const float g1 = tanhap(a), o1 = sig_h(b);
            upk(P2_0, a, b); const float i2 = sig_h(a), f2 = sig_h(b);
            upk(P2_1, a, b); const float g2 = tanhap(a), o2 = sig_h(b);

            c1 = fmaf(f1, c1, i1 * g1);
            c2 = fmaf(f2, c2, i2 * g2);
            const float h1o = o1 * tanhap(c1);
            const float h2o = o2 * tanhap(c2);

            #pragma unroll
            for (int k = 0; k < H; k++) {
                const float v1 = __shfl_sync(0xffffffffu, h1o, k, 8);
                const float v2 = __shfl_sync(0xffffffffu, h2o, k, 8);
                h1p[k] = pk2(v1, v1);
                h2p[k] = pk2(v2, v2);
            }
        }
        xv = xn;
    }
    // loop produced h2 = h2(T-1); the final (extra) L1 result is unused.

    // ---- FC head: out[e][j] = b_fc[j] + sum_k Wfc[j][k]*h2[k], j < 4 ----
    if (j < 4) {
        float acc = bfc[j];
        #pragma unroll
        for (int k = 0; k < H; k++) {
            float lo, hi;
            upk(h2p[k], lo, hi);
            acc = fmaf(Wfc[j * H + k], lo, acc);
        }
        out[e * 4 + j] = acc;
    }
}

extern "C" void kernel_launch(void* const* d_in, const int* in_sizes, int n_in,
                              void* d_out, int out_size)
{
    const float* x    = (const float*)d_in[0];
    const float* Wih1 = (const float*)d_in[1];
    const float* Whh1 = (const float*)d_in[2];
    const float* bih1 = (const float*)d_in[3];
    const float* bhh1 = (const float*)d_in[4];
    const float* Wih2 = (const float*)d_in[5];
    const float* Whh2 = (const float*)d_in[6];
    const float* bih2 = (const float*)d_in[7];
    const float* bhh2 = (const float*)d_in[8];
    const float* Wfc  = (const float*)d_in[9];
    const float* bfc  = (const float*)d_in[10];
    float* out = (float*)d_out;

    const int B = 4096;
    dim3 grid(B * 8 / 32), block(32);
    lstm2_kernel<<<grid, block>>>(x, Wih1, Whh1, bih1, bhh1,
                                  Wih2, Whh2, bih2, bhh2, Wfc, bfc, out);
}